// round 9
// baseline (speedup 1.0000x reference)
#include <cuda_runtime.h>
#include <cstddef>

#define N_ROWS 8192
#define N_COLS 8192
#define THREADS 256
#define N_STEPS 100
#define EPT (N_COLS / 64)   // elements per thread within a 64-thread group = 128
#define MAXC 26             // max steps per group

__device__ __forceinline__ float shfl_add(float v) {
    #pragma unroll
    for (int o = 16; o; o >>= 1) v += __shfl_xor_sync(0xFFFFFFFFu, v, o);
    return v;
}

// ---------- Route A: magic-constant rounding (R4-identical, fma-pipe 10 cyc/pair)
// u = |x|*inv;  rr = fma(|x|,inv,M) = M + round(u); rr = min(rr, M+cb);
// nq = M - rr = -q (exact); dd = fma(|x|,inv,nq) = u - q; acc += dd*dd
template<int NP>
__device__ __forceinline__ void run_group_magic(
    const float* __restrict__ row_sm, const float* __restrict__ invs,
    float (*partial)[MAXC], int base, int l64, int warp, int lane,
    unsigned long long M2)
{
    unsigned long long ivp[NP], app[NP];
    #pragma unroll
    for (int j = 0; j < NP; j++) {
        float a = invs[base + 2 * j], b = invs[base + 2 * j + 1];
        asm("mov.b64 %0, {%1,%2};" : "=l"(ivp[j]) : "f"(a), "f"(b));
        app[j] = 0ULL;
    }

    #pragma unroll 2
    for (int k = 0; k < EPT; k++) {
        float xv = row_sm[l64 + (k << 6)];
        unsigned xb = __float_as_uint(xv);
        float ax = __uint_as_float(xb & 0x7FFFFFFFu);                  // |x|
        float cb = __uint_as_float(0x4B40007Fu + (xb >> 31));          // M+127/M+128
        unsigned long long aa;
        asm("mov.b64 %0, {%1,%1};" : "=l"(aa) : "f"(ax));
        #pragma unroll
        for (int j = 0; j < NP; j++) {
            asm("{\n\t"
                ".reg .f32 n0,n1;\n\t"
                ".reg .b64 rr,nq,dd;\n\t"
                "fma.rn.f32x2 rr, %1, %2, %3;\n\t"   // M + round(u)   [fma rt3]
                "mov.b64 {n0,n1}, rr;\n\t"
                "min.f32 n0, n0, %4;\n\t"            // clamp          [alu]
                "min.f32 n1, n1, %4;\n\t"
                "mov.b64 rr, {n0,n1};\n\t"
                "sub.rn.f32x2 nq, %3, rr;\n\t"       // -q exact       [fma rt2]
                "fma.rn.f32x2 dd, %1, %2, nq;\n\t"   // u - q          [fma rt3]
                "fma.rn.f32x2 %0, dd, dd, %0;\n\t"   // acc += d*d     [fma rt2]
                "}"
                : "+l"(app[j])
                : "l"(aa), "l"(ivp[j]), "l"(M2), "f"(cb));
        }
    }

    #pragma unroll
    for (int j = 0; j < NP; j++) {
        float a0, a1;
        asm("mov.b64 {%0,%1}, %2;" : "=f"(a0), "=f"(a1) : "l"(app[j]));
        a0 = shfl_add(a0);
        a1 = shfl_add(a1);
        if (lane == 0) { partial[warp][2 * j] = a0; partial[warp][2 * j + 1] = a1; }
    }
}

// ---------- Route B: F2I/I2F rounding (fma-pipe 6 cyc/pair; rounding on cvt path)
// u = |x|*inv; uc = min(u, cb) with cb = 127.0 / 128.0 (clamp-before-round ==
// round-then-clamp for integer bounds); q = I2F(F2I.rni(uc));
// dd = u - q; acc += dd*dd.
template<int NP>
__device__ __forceinline__ void run_group_cvt(
    const float* __restrict__ row_sm, const float* __restrict__ invs,
    float (*partial)[MAXC], int base, int l64, int warp, int lane)
{
    unsigned long long ivp[NP], app[NP];
    #pragma unroll
    for (int j = 0; j < NP; j++) {
        float a = invs[base + 2 * j], b = invs[base + 2 * j + 1];
        asm("mov.b64 %0, {%1,%2};" : "=l"(ivp[j]) : "f"(a), "f"(b));
        app[j] = 0ULL;
    }

    #pragma unroll 2
    for (int k = 0; k < EPT; k++) {
        float xv = row_sm[l64 + (k << 6)];
        unsigned xb = __float_as_uint(xv);
        float ax  = __uint_as_float(xb & 0x7FFFFFFFu);                 // |x|
        float cbf = __uint_as_float(0x42FE0000u + ((xb >> 31) << 17)); // 127/128
        unsigned long long aa;
        asm("mov.b64 %0, {%1,%1};" : "=l"(aa) : "f"(ax));
        #pragma unroll
        for (int j = 0; j < NP; j++) {
            asm("{\n\t"
                ".reg .f32 u0,u1,c0,c1,q0,q1;\n\t"
                ".reg .s32 i0,i1;\n\t"
                ".reg .b64 uu,qq,dd;\n\t"
                "mul.rn.f32x2 uu, %1, %2;\n\t"       // u = |x|*inv    [fma rt2]
                "mov.b64 {u0,u1}, uu;\n\t"
                "min.f32 c0, u0, %3;\n\t"            // clamp          [alu]
                "min.f32 c1, u1, %3;\n\t"
                "cvt.rni.s32.f32 i0, c0;\n\t"        // round-half-even [cvt]
                "cvt.rni.s32.f32 i1, c1;\n\t"
                "cvt.rn.f32.s32 q0, i0;\n\t"         // q back to f32   [cvt]
                "cvt.rn.f32.s32 q1, i1;\n\t"
                "mov.b64 qq, {q0,q1};\n\t"
                "sub.rn.f32x2 dd, uu, qq;\n\t"       // u - q          [fma rt2]
                "fma.rn.f32x2 %0, dd, dd, %0;\n\t"   // acc += d*d     [fma rt2]
                "}"
                : "+l"(app[j])
                : "l"(aa), "l"(ivp[j]), "f"(cbf));
        }
    }

    #pragma unroll
    for (int j = 0; j < NP; j++) {
        float a0, a1;
        asm("mov.b64 {%0,%1}, %2;" : "=f"(a0), "=f"(a1) : "l"(app[j]));
        a0 = shfl_add(a0);
        a1 = shfl_add(a1);
        if (lane == 0) { partial[warp][2 * j] = a0; partial[warp][2 * j + 1] = a1; }
    }
}

__global__ __launch_bounds__(THREADS)
void mse_observer_kernel(const float* __restrict__ x, float* __restrict__ out,
                         unsigned long long M2) {
    __shared__ float row_sm[N_COLS];
    __shared__ float invs[N_STEPS];        // 1/scale_i
    __shared__ float s2k[N_STEPS];         // scale_i^2 / 8192
    __shared__ float thr_sm[N_STEPS];      // thres_i
    __shared__ float partial[8][MAXC];     // per-warp partial sums (group-local)
    __shared__ float red_min[8], red_max[8];
    __shared__ float losses[N_STEPS];
    __shared__ float Rsh, rmin_sh, rmax_sh;

    const int row  = blockIdx.x;
    const int tid  = threadIdx.x;
    const int warp = tid >> 5;
    const int lane = tid & 31;
    const float* xr = x + (size_t)row * N_COLS;

    // ---- Phase A: load row to smem, compute row min/max ----
    float mn = 3.0e38f, mx = -3.0e38f;
    const float4* xr4 = (const float4*)xr;
    float4* row4 = (float4*)row_sm;
    #pragma unroll
    for (int k = 0; k < N_COLS / 4 / THREADS; k++) {   // 8 iterations
        float4 v = xr4[tid + k * THREADS];
        row4[tid + k * THREADS] = v;
        mn = fminf(mn, fminf(fminf(v.x, v.y), fminf(v.z, v.w)));
        mx = fmaxf(mx, fmaxf(fmaxf(v.x, v.y), fmaxf(v.z, v.w)));
    }
    #pragma unroll
    for (int o = 16; o; o >>= 1) {
        mn = fminf(mn, __shfl_xor_sync(0xFFFFFFFFu, mn, o));
        mx = fmaxf(mx, __shfl_xor_sync(0xFFFFFFFFu, mx, o));
    }
    if (lane == 0) { red_min[warp] = mn; red_max[warp] = mx; }
    __syncthreads();
    if (tid == 0) {
        float m = red_min[0], M = red_max[0];
        #pragma unroll
        for (int w = 1; w < 8; w++) { m = fminf(m, red_min[w]); M = fmaxf(M, red_max[w]); }
        rmin_sh = m; rmax_sh = M;
        Rsh = fmaxf(fabsf(m), M);   // range_val = max(|min|, max)
    }
    __syncthreads();

    // ---- Phase B: per-step tables ----
    if (tid < N_STEPS) {
        float R = Rsh;
        float thres = __fdiv_rn(R, 100.0f) * (float)(tid + 1);
        float scale = fmaxf(__fdiv_rn(thres, 127.5f), 1.1920928955078125e-07f);
        thr_sm[tid] = thres;
        invs[tid]   = __fdiv_rn(1.0f, scale);
        s2k[tid]    = scale * scale * (1.0f / 8192.0f);
    }
    __syncthreads();

    // ---- Phase C: mixed-route. Groups 0,1: magic (12 pairs; steps 0..23,24..47)
    //                            Groups 2,3: cvt   (13 pairs; steps 48..73,74..99)
    // Warps of both kinds coexist per SMSP, averaging fma-pipe load to 8 cyc/pair.
    const int grp = tid >> 6;
    const int l64 = tid & 63;
    if (grp == 0)      run_group_magic<12>(row_sm, invs, partial,  0, l64, warp, lane, M2);
    else if (grp == 1) run_group_magic<12>(row_sm, invs, partial, 24, l64, warp, lane, M2);
    else if (grp == 2) run_group_cvt<13>(row_sm, invs, partial, 48, l64, warp, lane);
    else               run_group_cvt<13>(row_sm, invs, partial, 74, l64, warp, lane);
    __syncthreads();

    // ---- Phase D: combine warp pairs into losses ----
    if (tid < N_STEPS) {
        int s = tid;
        int g, jj;
        if (s < 48) { g = s / 24; jj = s - 24 * g; }
        else        { g = 2 + (s - 48) / 26; jj = (s - 48) % 26; }
        float sum = partial[2 * g][jj] + partial[2 * g + 1][jj];
        losses[s] = sum * s2k[s];   // mean((xq-x)^2)
    }
    __syncthreads();

    // ---- Phase E: sequential argmin scan (matches lax.scan semantics) ----
    if (tid == 0) {
        float best = 1.0e9f;
        float bmin = rmin_sh, bmax = rmax_sh;
        for (int j = 0; j < N_STEPS; j++) {
            float L = losses[j];
            if (L < best) { best = L; bmin = -thr_sm[j]; bmax = thr_sm[j]; }
        }
        out[row] = bmin;
        out[N_ROWS + row] = bmax;
    }
}

extern "C" void kernel_launch(void* const* d_in, const int* in_sizes, int n_in,
                              void* d_out, int out_size) {
    const float* x = (const float*)d_in[0];
    float* out = (float*)d_out;
    mse_observer_kernel<<<N_ROWS, THREADS>>>(x, out, 0x4B4000004B400000ULL);
}

// round 10
// speedup vs baseline: 1.2009x; 1.2009x over previous
#include <cuda_runtime.h>
#include <cstddef>

#define N_ROWS 8192
#define N_COLS 8192
#define THREADS 256
#define N_STEPS 100
#define HALF_STEPS 50
#define EPT (N_COLS / 64)   // elements per thread within a 64-thread group = 128
#define MAXC 14             // max local steps per group (group 3 has 14)

// Cross-kernel scratch (device globals: allowed; no allocation).
__device__ float g_loss[N_STEPS][N_ROWS];   // losses[step][row]
__device__ float g_aux[2][N_ROWS];          // [0]=rmin, [1]=rmax per row

__device__ __forceinline__ float shfl_add(float v) {
    #pragma unroll
    for (int o = 16; o; o >>= 1) v += __shfl_xor_sync(0xFFFFFFFFu, v, o);
    return v;
}

// R4-identical math. 64-thread group evaluates NP packed step-pairs.
// u = |x|*inv;  rr = fma(|x|,inv,M) = M + round(u)  (exact; huge u clamped)
// rr = min(rr, M+cb), cb = 127 (x>=0) / 128 (x<0)
// nq = M - rr = -q (exact);  dd = fma(|x|,inv,nq) = u - q;  acc += dd*dd
template<int NP>
__device__ __forceinline__ void run_group(
    const float* __restrict__ row_sm, const float* __restrict__ invs,
    float (*partial)[MAXC], int base, int l64, int warp, int lane,
    unsigned long long M2)
{
    unsigned long long ivp[NP], app[NP];
    #pragma unroll
    for (int j = 0; j < NP; j++) {
        float a = invs[base + 2 * j], b = invs[base + 2 * j + 1];
        asm("mov.b64 %0, {%1,%2};" : "=l"(ivp[j]) : "f"(a), "f"(b));
        app[j] = 0ULL;
    }

    #pragma unroll 2
    for (int k = 0; k < EPT; k++) {
        float xv = row_sm[l64 + (k << 6)];
        unsigned xb = __float_as_uint(xv);
        float ax = __uint_as_float(xb & 0x7FFFFFFFu);            // |x|
        float cb = __uint_as_float(0x4B40007Fu + (xb >> 31));    // M+127 / M+128
        unsigned long long aa;
        asm("mov.b64 %0, {%1,%1};" : "=l"(aa) : "f"(ax));
        #pragma unroll
        for (int j = 0; j < NP; j++) {
            asm("{\n\t"
                ".reg .f32 n0,n1;\n\t"
                ".reg .b64 rr,nq,dd;\n\t"
                "fma.rn.f32x2 rr, %1, %2, %3;\n\t"   // M + round(u)   [fma]
                "mov.b64 {n0,n1}, rr;\n\t"
                "min.f32 n0, n0, %4;\n\t"            // clamp          [alu]
                "min.f32 n1, n1, %4;\n\t"
                "mov.b64 rr, {n0,n1};\n\t"
                "sub.rn.f32x2 nq, %3, rr;\n\t"       // -q exact       [fma]
                "fma.rn.f32x2 dd, %1, %2, nq;\n\t"   // u - q          [fma]
                "fma.rn.f32x2 %0, dd, dd, %0;\n\t"   // acc += d*d     [fma]
                "}"
                : "+l"(app[j])
                : "l"(aa), "l"(ivp[j]), "l"(M2), "f"(cb));
        }
    }

    #pragma unroll
    for (int j = 0; j < NP; j++) {
        float a0, a1;
        asm("mov.b64 {%0,%1}, %2;" : "=f"(a0), "=f"(a1) : "l"(app[j]));
        a0 = shfl_add(a0);
        a1 = shfl_add(a1);
        if (lane == 0) { partial[warp][2 * j] = a0; partial[warp][2 * j + 1] = a1; }
    }
}

// Kernel 1: grid (N_ROWS, 2). blockIdx.y selects which 50 steps this block owns.
__global__ __launch_bounds__(THREADS)
void mse_losses_kernel(const float* __restrict__ x, unsigned long long M2) {
    __shared__ float row_sm[N_COLS];
    __shared__ float invs[HALF_STEPS];     // 1/scale for this half's steps
    __shared__ float s2k[HALF_STEPS];      // scale^2 / 8192
    __shared__ float partial[8][MAXC];     // per-warp partials (group-local idx)
    __shared__ float red_min[8], red_max[8];
    __shared__ float Rsh, rmin_sh, rmax_sh;

    const int row  = blockIdx.x;
    const int half = blockIdx.y;
    const int tid  = threadIdx.x;
    const int warp = tid >> 5;
    const int lane = tid & 31;
    const float* xr = x + (size_t)row * N_COLS;

    // ---- Phase A: load row to smem, compute row min/max ----
    float mn = 3.0e38f, mx = -3.0e38f;
    const float4* xr4 = (const float4*)xr;
    float4* row4 = (float4*)row_sm;
    #pragma unroll
    for (int k = 0; k < N_COLS / 4 / THREADS; k++) {   // 8 iterations
        float4 v = xr4[tid + k * THREADS];
        row4[tid + k * THREADS] = v;
        mn = fminf(mn, fminf(fminf(v.x, v.y), fminf(v.z, v.w)));
        mx = fmaxf(mx, fmaxf(fmaxf(v.x, v.y), fmaxf(v.z, v.w)));
    }
    #pragma unroll
    for (int o = 16; o; o >>= 1) {
        mn = fminf(mn, __shfl_xor_sync(0xFFFFFFFFu, mn, o));
        mx = fmaxf(mx, __shfl_xor_sync(0xFFFFFFFFu, mx, o));
    }
    if (lane == 0) { red_min[warp] = mn; red_max[warp] = mx; }
    __syncthreads();
    if (tid == 0) {
        float m = red_min[0], M = red_max[0];
        #pragma unroll
        for (int w = 1; w < 8; w++) { m = fminf(m, red_min[w]); M = fmaxf(M, red_max[w]); }
        rmin_sh = m; rmax_sh = M;
        Rsh = fmaxf(fabsf(m), M);   // range_val = max(|min|, max)
        if (half == 0) {            // write aux once (k2 recomputes R identically)
            g_aux[0][row] = m;
            g_aux[1][row] = M;
        }
    }
    __syncthreads();

    // ---- Phase B: per-step tables for this half's 50 steps ----
    if (tid < HALF_STEPS) {
        float R = Rsh;
        int   sg = half * HALF_STEPS + tid;          // global step index 0..99
        float thres = __fdiv_rn(R, 100.0f) * (float)(sg + 1);
        float scale = fmaxf(__fdiv_rn(thres, 127.5f), 1.1920928955078125e-07f);
        invs[tid] = __fdiv_rn(1.0f, scale);
        s2k[tid]  = scale * scale * (1.0f / 8192.0f);
    }
    __syncthreads();

    // ---- Phase C: 4 groups x {6,6,6,7} pairs = 25 pairs = 50 steps ----
    const int grp = tid >> 6;
    const int l64 = tid & 63;
    if (grp == 0)      run_group<6>(row_sm, invs, partial,  0, l64, warp, lane, M2);
    else if (grp == 1) run_group<6>(row_sm, invs, partial, 12, l64, warp, lane, M2);
    else if (grp == 2) run_group<6>(row_sm, invs, partial, 24, l64, warp, lane, M2);
    else               run_group<7>(row_sm, invs, partial, 36, l64, warp, lane, M2);
    __syncthreads();

    // ---- Phase D: combine warp pairs, write losses to scratch ----
    if (tid < HALF_STEPS) {
        int s = tid;                       // local step 0..49
        int g  = (s < 36) ? (s / 12) : 3;
        int jj = (s < 36) ? (s % 12) : (s - 36);
        float sum = partial[2 * g][jj] + partial[2 * g + 1][jj];
        g_loss[half * HALF_STEPS + s][row] = sum * s2k[s];
    }
}

// Kernel 2: per-row sequential argmin scan (matches lax.scan semantics).
__global__ __launch_bounds__(256)
void mse_argmin_kernel(float* __restrict__ out) {
    int row = blockIdx.x * 256 + threadIdx.x;
    if (row >= N_ROWS) return;
    float rmin = g_aux[0][row];
    float rmax = g_aux[1][row];
    float R = fmaxf(fabsf(rmin), rmax);
    float step_sz = __fdiv_rn(R, 100.0f);      // identical expr to kernel1
    float best = 1.0e9f;
    float bmin = rmin, bmax = rmax;
    for (int j = 0; j < N_STEPS; j++) {
        float L = g_loss[j][row];               // coalesced, L2-hot
        float thres = step_sz * (float)(j + 1);
        if (L < best) { best = L; bmin = -thres; bmax = thres; }
    }
    out[row] = bmin;
    out[N_ROWS + row] = bmax;
}

extern "C" void kernel_launch(void* const* d_in, const int* in_sizes, int n_in,
                              void* d_out, int out_size) {
    const float* x = (const float*)d_in[0];
    float* out = (float*)d_out;
    dim3 grid1(N_ROWS, 2);
    mse_losses_kernel<<<grid1, THREADS>>>(x, 0x4B4000004B400000ULL);
    mse_argmin_kernel<<<N_ROWS / 256, 256>>>(out);
}